// round 15
// baseline (speedup 1.0000x reference)
#include <cuda_runtime.h>

// ValueLayerSlow: Pauli expectation values <psi|O|psi> for 16 Pauli strings on
// 10 qubits (dim=1024), states are REAL vectors (8*512 = 4096 states).
//
//   Z on d-bit b (op o -> bit 9-o): sum_d (-1)^{bit_b(d)} x_d^2
//   X masks 512/256/128 (ops 10,11,12): 2 * sum_{pairs} x_d x_{d^m}
//   Y ops (13,14,15): exactly 0.
//
// R15: TWO states per warp, ALL 16 LDG.128 issued before any compute.
// Little's-law fix: achieved HBM BW was pinned at ~2.3 TB/s because each
// warp kept only ~2KB in flight (4+4 split). Doubling in-flight bytes per
// warp (8KB) doubles the bandwidth ceiling; compute doubles too, but issue
// was at 20% (R13 showed instruction count is not binding).
// Per-state math = R12's proven pipeline (scalar squares/dots, merge-tree
// reduction with 9 shuffles, WH butterfly, single coalesced STG).

__device__ __forceinline__ float merge2(float a, float b, int bit, int lane) {
    bool hi = (lane & bit) != 0;
    float keep = hi ? b : a;
    float send = hi ? a : b;
    float recv = __shfl_xor_sync(0xFFFFFFFFu, send, bit);
    return keep + recv;
}

__device__ __forceinline__ void process_state(const float4 v[8],
                                              float* __restrict__ o,
                                              int lane) {
    float s[8];
    float z1 = 0.f, z0 = 0.f;
#pragma unroll
    for (int i = 0; i < 8; i++) {
        float a0 = v[i].x * v[i].x, a1 = v[i].y * v[i].y;
        float a2 = v[i].z * v[i].z, a3 = v[i].w * v[i].w;
        float p01 = a0 + a1, p23 = a2 + a3;
        s[i] = p01 + p23;
        z1 += p01 - p23;
        z0 += (a0 - a1) + (a2 - a3);
    }

    float e01 = s[0] + s[1], e23 = s[2] + s[3];
    float e45 = s[4] + s[5], e67 = s[6] + s[7];
    float S  = (e01 + e23) + (e45 + e67);
    float z9 = (e01 + e23) - (e45 + e67);          // op0 (i bit2)
    float z8 = (e01 + e45) - (e23 + e67);          // op1 (i bit1)
    float z7 = ((s[0] + s[2]) + (s[4] + s[6]))
             - ((s[1] + s[3]) + (s[5] + s[7]));    // op2 (i bit0)

#define DOT4(a, b) ((a).x*(b).x + (a).y*(b).y + (a).z*(b).z + (a).w*(b).w)
    float x9 = DOT4(v[0], v[4]) + DOT4(v[1], v[5])
             + DOT4(v[2], v[6]) + DOT4(v[3], v[7]);   // mask 512 (op10)
    float x8 = DOT4(v[0], v[2]) + DOT4(v[1], v[3])
             + DOT4(v[4], v[6]) + DOT4(v[5], v[7]);   // mask 256 (op11)
    float x7 = DOT4(v[0], v[1]) + DOT4(v[2], v[3])
             + DOT4(v[4], v[5]) + DOT4(v[6], v[7]);   // mask 128 (op12)
#undef DOT4

    // split-merge reduction: 9 shuffles for all 8 scalars.
    const unsigned FULL = 0xFFFFFFFFu;
    float m0 = merge2(z9, z8, 16, lane);
    float m1 = merge2(z7, z1, 16, lane);
    float m2 = merge2(z0, x9, 16, lane);
    float m3 = merge2(x8, x7, 16, lane);
    float n0 = merge2(m0, m1, 8, lane);
    float n1 = merge2(m2, m3, 8, lane);
    float q  = merge2(n0, n1, 4, lane);
    q += __shfl_xor_sync(FULL, q, 2);
    q += __shfl_xor_sync(FULL, q, 1);
    // scalar k (z9,z8,z7,z1,z0,x9,x8,x7 = k 0..7) at lanes 4*bitrev3(k)

    // Walsh-Hadamard over S: lane 2^k holds Z on d-bit (k+2) = op (7-k)
    float w = S;
#pragma unroll
    for (int k = 0; k < 5; k++) {
        float p = __shfl_xor_sync(FULL, w, 1 << k);
        w = (lane & (1 << k)) ? (p - w) : (p + w);
    }
    int srcw = (lane >= 3 && lane < 8) ? (1 << (7 - lane)) : 0;
    float wmv = __shfl_sync(FULL, w, srcw);

    int k   = (lane < 3) ? lane : (lane - 5);
    int srq = (((k & 1) << 2) | (k & 2) | ((k & 4) >> 2)) << 2;
    float qv = __shfl_sync(FULL, q, srq & 31);

    float val = (lane < 3)  ? qv
              : (lane < 8)  ? wmv
              : (lane < 10) ? qv
              : (lane < 13) ? 2.0f * qv
              : 0.0f;                             // ops 13,14,15 (Y) = 0
    if (lane < 16) o[lane] = val;
}

__global__ void __launch_bounds__(64)
pauli_expect_kernel(const float* __restrict__ x, float* __restrict__ out,
                    int n_states) {
    const int wg   = (blockIdx.x * blockDim.x + threadIdx.x) >> 5;
    const int lane = threadIdx.x & 31;
    const int s0   = wg * 2;
    if (s0 >= n_states) return;

    const float4* xp0 = reinterpret_cast<const float4*>(x) + (size_t)s0 * 256;
    const float4* xp1 = xp0 + 256;

    // ---- all 16 loads issued before any compute (8KB in flight per warp)
    float4 va[8], vb[8];
#pragma unroll
    for (int i = 0; i < 8; i++) va[i] = xp0[i * 32 + lane];
#pragma unroll
    for (int i = 0; i < 8; i++) vb[i] = xp1[i * 32 + lane];

    process_state(va, out + (size_t)s0 * 16, lane);
    process_state(vb, out + (size_t)(s0 + 1) * 16, lane);
}

extern "C" void kernel_launch(void* const* d_in, const int* in_sizes, int n_in,
                              void* d_out, int out_size) {
    const float* x = (const float*)d_in[0];
    float* out = (float*)d_out;
    const int n_states = in_sizes[0] / 1024;     // 4096 for (8,512,1024)
    // 2 states per warp, 2 warps (64 thr) per block -> 4 states per block
    const int blocks = (n_states + 3) / 4;
    pauli_expect_kernel<<<blocks, 64>>>(x, out, n_states);
}

// round 16
// speedup vs baseline: 1.1333x; 1.1333x over previous
#include <cuda_runtime.h>

// ValueLayerSlow: Pauli expectation values <psi|O|psi> for 16 Pauli strings on
// 10 qubits (dim=1024), states are REAL vectors (8*512 = 4096 states).
//
//   Z on d-bit b (op o -> bit 9-o): sum_d (-1)^{bit_b(d)} x_d^2
//   X masks 512/256/128 (ops 10,11,12): 2 * sum_{pairs} x_d x_{d^m}
//   Y ops (13,14,15): exactly 0.
//
// R16: grid-stride ping-pong pipeline. 296 blocks (2/SM exactly) x 4 warps;
// each warp processes ~3.46 states, issuing state k+1's 8 LDG.128 BEFORE
// computing state k. Steady-state: the ~460-cycle compute body covers the
// 577-cycle DRAM latency; the latency head is paid once per warp, not once
// per state. Per-state math = R12's proven pipeline (scalar squares/dots,
// merge-tree reduction, WH butterfly, single coalesced STG).

__device__ __forceinline__ float merge2(float a, float b, int bit, int lane) {
    bool hi = (lane & bit) != 0;
    float keep = hi ? b : a;
    float send = hi ? a : b;
    float recv = __shfl_xor_sync(0xFFFFFFFFu, send, bit);
    return keep + recv;
}

__device__ __forceinline__ void load_state(const float* __restrict__ x,
                                           int state, int lane, float4 v[8]) {
    const float4* xp = reinterpret_cast<const float4*>(x) + (size_t)state * 256;
#pragma unroll
    for (int i = 0; i < 8; i++) v[i] = xp[i * 32 + lane];
}

__device__ __forceinline__ void process_state(const float4 v[8],
                                              float* __restrict__ o,
                                              int lane) {
    float s[8];
    float z1 = 0.f, z0 = 0.f;
#pragma unroll
    for (int i = 0; i < 8; i++) {
        float a0 = v[i].x * v[i].x, a1 = v[i].y * v[i].y;
        float a2 = v[i].z * v[i].z, a3 = v[i].w * v[i].w;
        float p01 = a0 + a1, p23 = a2 + a3;
        s[i] = p01 + p23;
        z1 += p01 - p23;
        z0 += (a0 - a1) + (a2 - a3);
    }

    float e01 = s[0] + s[1], e23 = s[2] + s[3];
    float e45 = s[4] + s[5], e67 = s[6] + s[7];
    float S  = (e01 + e23) + (e45 + e67);
    float z9 = (e01 + e23) - (e45 + e67);          // op0 (i bit2)
    float z8 = (e01 + e45) - (e23 + e67);          // op1 (i bit1)
    float z7 = ((s[0] + s[2]) + (s[4] + s[6]))
             - ((s[1] + s[3]) + (s[5] + s[7]));    // op2 (i bit0)

#define DOT4(a, b) ((a).x*(b).x + (a).y*(b).y + (a).z*(b).z + (a).w*(b).w)
    float x9 = DOT4(v[0], v[4]) + DOT4(v[1], v[5])
             + DOT4(v[2], v[6]) + DOT4(v[3], v[7]);   // mask 512 (op10)
    float x8 = DOT4(v[0], v[2]) + DOT4(v[1], v[3])
             + DOT4(v[4], v[6]) + DOT4(v[5], v[7]);   // mask 256 (op11)
    float x7 = DOT4(v[0], v[1]) + DOT4(v[2], v[3])
             + DOT4(v[4], v[5]) + DOT4(v[6], v[7]);   // mask 128 (op12)
#undef DOT4

    // split-merge reduction: 9 shuffles for all 8 scalars.
    const unsigned FULL = 0xFFFFFFFFu;
    float m0 = merge2(z9, z8, 16, lane);
    float m1 = merge2(z7, z1, 16, lane);
    float m2 = merge2(z0, x9, 16, lane);
    float m3 = merge2(x8, x7, 16, lane);
    float n0 = merge2(m0, m1, 8, lane);
    float n1 = merge2(m2, m3, 8, lane);
    float q  = merge2(n0, n1, 4, lane);
    q += __shfl_xor_sync(FULL, q, 2);
    q += __shfl_xor_sync(FULL, q, 1);
    // scalar k (z9,z8,z7,z1,z0,x9,x8,x7 = k 0..7) at lanes 4*bitrev3(k)

    // Walsh-Hadamard over S: lane 2^k holds Z on d-bit (k+2) = op (7-k)
    float w = S;
#pragma unroll
    for (int k = 0; k < 5; k++) {
        float p = __shfl_xor_sync(FULL, w, 1 << k);
        w = (lane & (1 << k)) ? (p - w) : (p + w);
    }
    int srcw = (lane >= 3 && lane < 8) ? (1 << (7 - lane)) : 0;
    float wmv = __shfl_sync(FULL, w, srcw);

    int k   = (lane < 3) ? lane : (lane - 5);
    int srq = (((k & 1) << 2) | (k & 2) | ((k & 4) >> 2)) << 2;
    float qv = __shfl_sync(FULL, q, srq & 31);

    float val = (lane < 3)  ? qv
              : (lane < 8)  ? wmv
              : (lane < 10) ? qv
              : (lane < 13) ? 2.0f * qv
              : 0.0f;                             // ops 13,14,15 (Y) = 0
    if (lane < 16) o[lane] = val;
}

__global__ void __launch_bounds__(128)
pauli_expect_kernel(const float* __restrict__ x, float* __restrict__ out,
                    int n_states, int n_warps) {
    const int warp = (blockIdx.x * blockDim.x + threadIdx.x) >> 5;
    const int lane = threadIdx.x & 31;

    int s = warp;
    if (s >= n_states) return;

    float4 A[8], B[8];
    load_state(x, s, lane, A);

    while (true) {
        // prefetch next state into B while A computes
        int sB = s + n_warps;
        if (sB < n_states) load_state(x, sB, lane, B);
        process_state(A, out + (size_t)s * 16, lane);
        s = sB;
        if (s >= n_states) break;

        // prefetch next-next into A while B computes
        int sA = s + n_warps;
        if (sA < n_states) load_state(x, sA, lane, A);
        process_state(B, out + (size_t)s * 16, lane);
        s = sA;
        if (s >= n_states) break;
    }
}

extern "C" void kernel_launch(void* const* d_in, const int* in_sizes, int n_in,
                              void* d_out, int out_size) {
    const float* x = (const float*)d_in[0];
    float* out = (float*)d_out;
    const int n_states = in_sizes[0] / 1024;     // 4096 for (8,512,1024)
    const int blocks = 296;                      // exactly 2 blocks per SM
    const int n_warps = blocks * 4;              // 1184 warps, ~3.46 states ea
    pauli_expect_kernel<<<blocks, 128>>>(x, out, n_states, n_warps);
}

// round 17
// speedup vs baseline: 1.1697x; 1.0321x over previous
#include <cuda_runtime.h>

// ValueLayerSlow: Pauli expectation values <psi|O|psi> for 16 Pauli strings on
// 10 qubits (dim=1024), states are REAL vectors (8*512 = 4096 states).
//
//   Z on d-bit b (op o -> bit 9-o): sum_d (-1)^{bit_b(d)} x_d^2
//   X masks 512/256/128 (ops 10,11,12): 2 * sum_{pairs} x_d x_{d^m}
//   Y ops (13,14,15): exactly 0.
//
// FINAL (R13 structure, best measured 7.04us):
// One warp per state. Lane t holds d = i*128 + t*4 + j (8 x float4, kept as
// packed f32x2 pairs p01=(j0,j1), p23=(j2,j3)).
//  - 4+4 load split (MLP_p1=4, minimizes single-wave cross-CTA spread)
//  - packed f32x2 squares/dots, ILP-preserving (chains <= 4 deep)
//  - split-merge tree reduction: 9 shuffles for all 8 scalars
//  - Walsh-Hadamard butterfly for the 5 lane-bit Z ops
//  - one coalesced STG.32 across lanes 0..15
// Elimination experiments (R8 occupancy, R10 load policy, R11 shuffles,
// R13 instr count, R15 in-flight bytes, R16 pipelining) show the residual
// ~5us above the pure-BW floor is fixed per-replay overhead, not kernel work.

using ull = unsigned long long;

__device__ __forceinline__ ull mul2(ull a, ull b) {
    ull r; asm("mul.rn.f32x2 %0, %1, %2;" : "=l"(r) : "l"(a), "l"(b)); return r;
}
__device__ __forceinline__ ull add2(ull a, ull b) {
    ull r; asm("add.rn.f32x2 %0, %1, %2;" : "=l"(r) : "l"(a), "l"(b)); return r;
}
__device__ __forceinline__ ull sub2(ull a, ull b) {
    ull r; asm("sub.rn.f32x2 %0, %1, %2;" : "=l"(r) : "l"(a), "l"(b)); return r;
}
__device__ __forceinline__ ull fma2(ull a, ull b, ull c) {
    ull r; asm("fma.rn.f32x2 %0, %1, %2, %3;" : "=l"(r) : "l"(a), "l"(b), "l"(c)); return r;
}
__device__ __forceinline__ void upk(ull v, float& lo, float& hi) {
    asm("mov.b64 {%0, %1}, %2;" : "=f"(lo), "=f"(hi) : "l"(v));
}

// merge2: butterfly stage reducing a and b over `bit` while splitting their
// identity across that lane bit.
__device__ __forceinline__ float merge2(float a, float b, int bit, int lane) {
    bool hi = (lane & bit) != 0;
    float keep = hi ? b : a;
    float send = hi ? a : b;
    float recv = __shfl_xor_sync(0xFFFFFFFFu, send, bit);
    return keep + recv;
}

__global__ void __launch_bounds__(128)
pauli_expect_kernel(const float* __restrict__ x, float* __restrict__ out,
                    int n_states) {
    const int warp = (blockIdx.x * blockDim.x + threadIdx.x) >> 5;
    const int lane = threadIdx.x & 31;
    if (warp >= n_states) return;

    const ulonglong2* xp =
        reinterpret_cast<const ulonglong2*>(x) + (size_t)warp * 256;

    ull p01[8], p23[8];
    ull R[8];
    ull Da = 0ull, Db = 0ull;   // two accumulators for the j-bit1 Z partials

#define SQ(i, Dacc) { ull s01 = mul2(p01[i], p01[i]);                      \
                      ull s23 = mul2(p23[i], p23[i]);                      \
                      R[i] = add2(s01, s23);                               \
                      Dacc = add2(Dacc, sub2(s01, s23)); }

    // ---- batch 1: loads + squares (MLP_p1 = 4) ----
#pragma unroll
    for (int i = 0; i < 4; i++) {
        ulonglong2 t = xp[i * 32 + lane];
        p01[i] = t.x; p23[i] = t.y;
    }
    SQ(0, Da) SQ(1, Db) SQ(2, Da) SQ(3, Db)

    asm volatile("" ::: "memory");

    // ---- batch 2 ----
#pragma unroll
    for (int i = 4; i < 8; i++) {
        ulonglong2 t = xp[i * 32 + lane];
        p01[i] = t.x; p23[i] = t.y;
    }
    SQ(4, Da) SQ(5, Db) SQ(6, Da) SQ(7, Db)
#undef SQ

    // R[i] = p01^2 + p23^2 = (a0^2+a2^2, a1^2+a3^2):
    // lo sums j in {0,2}, hi sums j in {1,3}
    ull e01 = add2(R[0], R[1]), e23 = add2(R[2], R[3]);
    ull e45 = add2(R[4], R[5]), e67 = add2(R[6], R[7]);
    ull e0123 = add2(e01, e23), e4567 = add2(e45, e67);
    ull Sp  = add2(e0123, e4567);
    ull z9p = sub2(e0123, e4567);                       // i bit2 sign
    ull z8p = sub2(add2(e01, e45), add2(e23, e67));     // i bit1 sign
    ull oev = add2(add2(R[0], R[2]), add2(R[4], R[6]));
    ull odd = add2(add2(R[1], R[3]), add2(R[5], R[7]));
    ull z7p = sub2(oev, odd);                           // i bit0 sign

    float Slo, Shi, t0, t1;
    upk(Sp, Slo, Shi);
    float S  = Slo + Shi;       // per-lane sum of squares (for WH)
    float z0 = Slo - Shi;       // op9: j bit0 sign ((a0+a2)-(a1+a3))
    upk(add2(Da, Db), t0, t1);
    float z1 = t0 + t1;         // op8: j bit1 sign ((a0+a1)-(a2+a3))
    upk(z9p, t0, t1); float z9 = t0 + t1;   // op0
    upk(z8p, t0, t1); float z8 = t0 + t1;   // op1
    upk(z7p, t0, t1); float z7 = t0 + t1;   // op2

    // ---- X dots: six independent 4-deep fma2 chains ----
    ull A9a = 0ull, A9b = 0ull, A8a = 0ull, A8b = 0ull, A7a = 0ull, A7b = 0ull;
#pragma unroll
    for (int k = 0; k < 4; k++) {           // mask 512: (0,4)(1,5)(2,6)(3,7)
        A9a = fma2(p01[k], p01[k + 4], A9a);
        A9b = fma2(p23[k], p23[k + 4], A9b);
    }
    // mask 256: (0,2)(1,3)(4,6)(5,7)
    A8a = fma2(p01[0], p01[2], A8a); A8b = fma2(p23[0], p23[2], A8b);
    A8a = fma2(p01[1], p01[3], A8a); A8b = fma2(p23[1], p23[3], A8b);
    A8a = fma2(p01[4], p01[6], A8a); A8b = fma2(p23[4], p23[6], A8b);
    A8a = fma2(p01[5], p01[7], A8a); A8b = fma2(p23[5], p23[7], A8b);
#pragma unroll
    for (int k = 0; k < 4; k++) {           // mask 128: (0,1)(2,3)(4,5)(6,7)
        A7a = fma2(p01[2 * k], p01[2 * k + 1], A7a);
        A7b = fma2(p23[2 * k], p23[2 * k + 1], A7b);
    }
    upk(add2(A9a, A9b), t0, t1); float x9 = t0 + t1;
    upk(add2(A8a, A8b), t0, t1); float x8 = t0 + t1;
    upk(add2(A7a, A7b), t0, t1); float x7 = t0 + t1;

    // ---- split-merge reduction: 9 shuffles for all 8 scalars ----
    const unsigned FULL = 0xFFFFFFFFu;
    float m0 = merge2(z9, z8, 16, lane);
    float m1 = merge2(z7, z1, 16, lane);
    float m2 = merge2(z0, x9, 16, lane);
    float m3 = merge2(x8, x7, 16, lane);
    float n0 = merge2(m0, m1, 8, lane);
    float n1 = merge2(m2, m3, 8, lane);
    float q  = merge2(n0, n1, 4, lane);
    q += __shfl_xor_sync(FULL, q, 2);
    q += __shfl_xor_sync(FULL, q, 1);
    // scalar k (z9,z8,z7,z1,z0,x9,x8,x7 = k 0..7) sits in lanes 4*bitrev3(k)

    // ---- Walsh-Hadamard over S: lane 2^k holds Z on d-bit (k+2) = op (7-k)
    float w = S;
#pragma unroll
    for (int k = 0; k < 5; k++) {
        float p = __shfl_xor_sync(FULL, w, 1 << k);
        w = (lane & (1 << k)) ? (p - w) : (p + w);
    }
    int srcw = (lane >= 3 && lane < 8) ? (1 << (7 - lane)) : 0;
    float wmv = __shfl_sync(FULL, w, srcw);

    // route q to output lanes {0,1,2,8..12}; k = lane (<3) or lane-5
    int k   = (lane < 3) ? lane : (lane - 5);
    int srq = (((k & 1) << 2) | (k & 2) | ((k & 4) >> 2)) << 2;
    float qv = __shfl_sync(FULL, q, srq & 31);

    // ---- one coalesced STG.32: out[warp*16 + lane], lanes 0..15 ----
    float val = (lane < 3)  ? qv
              : (lane < 8)  ? wmv
              : (lane < 10) ? qv
              : (lane < 13) ? 2.0f * qv
              : 0.0f;                             // ops 13,14,15 (Y) = 0
    if (lane < 16) out[(size_t)warp * 16 + lane] = val;
}

extern "C" void kernel_launch(void* const* d_in, const int* in_sizes, int n_in,
                              void* d_out, int out_size) {
    const float* x = (const float*)d_in[0];
    float* out = (float*)d_out;
    const int n_states = in_sizes[0] / 1024;     // 4096 for (8,512,1024)
    const int blocks = (n_states + 3) / 4;       // 4 warps (128 thr) per block
    pauli_expect_kernel<<<blocks, 128>>>(x, out, n_states);
}